// round 5
// baseline (speedup 1.0000x reference)
#include <cuda_runtime.h>

#define NV_MAX 50000
#define HDIM 64

// -------- scratch (no allocs allowed) --------
__device__ float g_A[NV_MAX * HDIM];      // x@W0 + pe@W1 + msg_b1
__device__ float g_B[NV_MAX * HDIM];      // x@W2 + pe@W3
__device__ float g_P[NV_MAX * HDIM];      // pe@V0 + mpos_b1
__device__ float g_Q[NV_MAX * HDIM];      // pe@V1
__device__ float g_aggr[NV_MAX * HDIM];
__device__ float g_aggrp[NV_MAX * HDIM];

typedef unsigned long long ull_t;

__device__ __forceinline__ ull_t pack2(float lo, float hi) {
    ull_t r; asm("mov.b64 %0, {%1, %2};" : "=l"(r) : "f"(lo), "f"(hi)); return r;
}
__device__ __forceinline__ void unpack2(ull_t v, float& lo, float& hi) {
    asm("mov.b64 {%0, %1}, %2;" : "=f"(lo), "=f"(hi) : "l"(v));
}
__device__ __forceinline__ ull_t ffma2(ull_t a, ull_t b, ull_t c) {
    ull_t d; asm("fma.rn.f32x2 %0, %1, %2, %3;" : "=l"(d) : "l"(a), "l"(b), "l"(c)); return d;
}
__device__ __forceinline__ float silu_f(float x) {
    return __fdividef(x, 1.0f + __expf(-x));
}
__device__ __forceinline__ float tanh_f(float x) {
    float t = __expf(2.0f * x);
    return 1.0f - 2.0f * __fdividef(1.0f, t + 1.0f);
}

// ============================================================
// Kernel 1: node pre-projections  A,B,P,Q  (+ zero aggr bufs)
// ============================================================
__global__ void __launch_bounds__(256, 1) node_pre_kernel(
    const float* __restrict__ x, const float* __restrict__ pe,
    const float* __restrict__ msg_w1, const float* __restrict__ msg_b1,
    const float* __restrict__ mpos_w1, const float* __restrict__ mpos_b1,
    int N)
{
    extern __shared__ float sm[];
    float* sh_inT = sm;                   // [128][68]
    float* sh_W   = sh_inT + 128 * 68;    // [128][256]
    float* sh_b   = sh_W + 128 * 256;     // [256]

    int tid = threadIdx.x;
    for (int idx = tid; idx < 128 * 256; idx += 256) {
        int k = idx >> 8, c = idx & 255;
        float v;
        if (c < 64)        v = msg_w1[k * 64 + c];
        else if (c < 128)  v = msg_w1[(128 + k) * 64 + (c - 64)];
        else if (c < 192)  v = (k >= 64) ? mpos_w1[(k - 64) * 64 + (c - 128)] : 0.0f;
        else               v = (k >= 64) ? mpos_w1[k * 64 + (c - 192)] : 0.0f;
        sh_W[idx] = v;
    }
    {
        int c = tid;
        if (c < 256)
            sh_b[c] = (c < 64) ? msg_b1[c]
                     : ((c >= 128 && c < 192) ? mpos_b1[c - 128] : 0.0f);
    }

    int nb = blockIdx.x * 64;
    {
        int n = tid & 63, q = tid >> 6;   // q in 0..3
        int gn = nb + n;
        bool v = gn < N;
        #pragma unroll
        for (int kk = 0; kk < 32; kk++) {
            int k = q * 32 + kk;
            float val = 0.0f;
            if (v) val = (k < 64) ? x[(size_t)gn * 64 + k]
                                  : pe[(size_t)gn * 64 + (k - 64)];
            sh_inT[k * 68 + n] = val;
        }
        if (v) {  // zero aggregation buffers for this node (runs before edge kernel)
            float4 z = make_float4(0.f, 0.f, 0.f, 0.f);
            float4* a4 = (float4*)(g_aggr  + (size_t)gn * 64) + q * 4;
            float4* p4 = (float4*)(g_aggrp + (size_t)gn * 64) + q * 4;
            #pragma unroll
            for (int j = 0; j < 4; j++) { a4[j] = z; p4[j] = z; }
        }
    }
    __syncthreads();

    int tr = tid & 15, tc = tid >> 4;     // 4 nodes x 16 channels per thread
    int ncol = 4 * tr, cb = 16 * tc;

    ull_t acc[4][8];
    #pragma unroll
    for (int i = 0; i < 4; i++)
        #pragma unroll
        for (int j = 0; j < 8; j++) acc[i][j] = 0ULL;

    #pragma unroll 4
    for (int k = 0; k < 128; k++) {
        float4 h = *(const float4*)(sh_inT + k * 68 + ncol);
        const ulonglong2* wp = (const ulonglong2*)(sh_W + k * 256 + cb);
        ulonglong2 w0 = wp[0], w1 = wp[1], w2 = wp[2], w3 = wp[3];
        ull_t hh[4] = {pack2(h.x, h.x), pack2(h.y, h.y), pack2(h.z, h.z), pack2(h.w, h.w)};
        #pragma unroll
        for (int i = 0; i < 4; i++) {
            acc[i][0] = ffma2(hh[i], w0.x, acc[i][0]);
            acc[i][1] = ffma2(hh[i], w0.y, acc[i][1]);
            acc[i][2] = ffma2(hh[i], w1.x, acc[i][2]);
            acc[i][3] = ffma2(hh[i], w1.y, acc[i][3]);
            acc[i][4] = ffma2(hh[i], w2.x, acc[i][4]);
            acc[i][5] = ffma2(hh[i], w2.y, acc[i][5]);
            acc[i][6] = ffma2(hh[i], w3.x, acc[i][6]);
            acc[i][7] = ffma2(hh[i], w3.y, acc[i][7]);
        }
    }

    int sect = tc >> 2;                   // 0:A 1:B 2:P 3:Q
    int lc = (tc & 3) * 16;
    float* dst = (sect == 0) ? g_A : (sect == 1) ? g_B : (sect == 2) ? g_P : g_Q;
    float bv[16];
    #pragma unroll
    for (int j = 0; j < 16; j++) bv[j] = sh_b[cb + j];

    #pragma unroll
    for (int i = 0; i < 4; i++) {
        int gn = nb + ncol + i;
        if (gn < N) {
            float o[16];
            #pragma unroll
            for (int j = 0; j < 8; j++) unpack2(acc[i][j], o[2 * j], o[2 * j + 1]);
            #pragma unroll
            for (int j = 0; j < 16; j++) o[j] += bv[j];
            float4* d4 = (float4*)(dst + (size_t)gn * 64 + lc);
            d4[0] = make_float4(o[0], o[1], o[2], o[3]);
            d4[1] = make_float4(o[4], o[5], o[6], o[7]);
            d4[2] = make_float4(o[8], o[9], o[10], o[11]);
            d4[3] = make_float4(o[12], o[13], o[14], o[15]);
        }
    }
}

// ============================================================
// Kernel 2: edge kernel — h1/g1 elementwise + layer-2 GEMMs + scatter-add
// ============================================================
template <bool IS_TANH>
__device__ __forceinline__ void edge_gemm_path(
    const float* hT, const float* W, const float* bias, const int* recs,
    float* __restrict__ aggr, int ebase, int cb, int eb, int E)
{
    ull_t acc[4][4];
    #pragma unroll
    for (int i = 0; i < 4; i++)
        #pragma unroll
        for (int j = 0; j < 4; j++) acc[i][j] = 0ULL;

    #pragma unroll 8
    for (int k = 0; k < 64; k++) {
        float4 h = *(const float4*)(hT + k * 132 + ebase);
        ulonglong2 w0 = *(const ulonglong2*)(W + k * 64 + cb);
        ulonglong2 w1 = *(const ulonglong2*)(W + k * 64 + cb + 4);
        ull_t h0 = pack2(h.x, h.x), h1 = pack2(h.y, h.y);
        ull_t h2 = pack2(h.z, h.z), h3 = pack2(h.w, h.w);
        acc[0][0] = ffma2(h0, w0.x, acc[0][0]); acc[0][1] = ffma2(h0, w0.y, acc[0][1]);
        acc[0][2] = ffma2(h0, w1.x, acc[0][2]); acc[0][3] = ffma2(h0, w1.y, acc[0][3]);
        acc[1][0] = ffma2(h1, w0.x, acc[1][0]); acc[1][1] = ffma2(h1, w0.y, acc[1][1]);
        acc[1][2] = ffma2(h1, w1.x, acc[1][2]); acc[1][3] = ffma2(h1, w1.y, acc[1][3]);
        acc[2][0] = ffma2(h2, w0.x, acc[2][0]); acc[2][1] = ffma2(h2, w0.y, acc[2][1]);
        acc[2][2] = ffma2(h2, w1.x, acc[2][2]); acc[2][3] = ffma2(h2, w1.y, acc[2][3]);
        acc[3][0] = ffma2(h3, w0.x, acc[3][0]); acc[3][1] = ffma2(h3, w0.y, acc[3][1]);
        acc[3][2] = ffma2(h3, w1.x, acc[3][2]); acc[3][3] = ffma2(h3, w1.y, acc[3][3]);
    }

    float bsv[8];
    #pragma unroll
    for (int j = 0; j < 8; j++) bsv[j] = bias[cb + j];

    #pragma unroll
    for (int i = 0; i < 4; i++) {
        int el = ebase + i;
        if (eb + el < E) {
            float m[8];
            unpack2(acc[i][0], m[0], m[1]);
            unpack2(acc[i][1], m[2], m[3]);
            unpack2(acc[i][2], m[4], m[5]);
            unpack2(acc[i][3], m[6], m[7]);
            #pragma unroll
            for (int j = 0; j < 8; j++) {
                float v = m[j] + bsv[j];
                m[j] = IS_TANH ? tanh_f(v) : silu_f(v);
            }
            float* dst = aggr + (size_t)recs[el] * 64 + cb;
            asm volatile("red.global.add.v4.f32 [%0], {%1,%2,%3,%4};"
                         :: "l"(dst), "f"(m[0]), "f"(m[1]), "f"(m[2]), "f"(m[3]) : "memory");
            asm volatile("red.global.add.v4.f32 [%0], {%1,%2,%3,%4};"
                         :: "l"(dst + 4), "f"(m[4]), "f"(m[5]), "f"(m[6]), "f"(m[7]) : "memory");
        }
    }
}

__global__ void __launch_bounds__(256, 2) edge_kernel(
    const float* __restrict__ pos,
    const int* __restrict__ ei,          // int32! (JAX demotes int64 -> int32)
    const float* __restrict__ msg_w1,
    const float* __restrict__ msg_w2, const float* __restrict__ msg_b2,
    const float* __restrict__ mpos_w1,
    const float* __restrict__ mpos_w2, const float* __restrict__ mpos_b2,
    int E)
{
    extern __shared__ float sm[];
    float* sh_h1t = sm;                    // [64][132]
    float* sh_g1t = sh_h1t + 64 * 132;     // [64][132]
    float* sh_Wm  = sh_g1t + 64 * 132;     // [64][64]
    float* sh_Wp  = sh_Wm + 64 * 64;       // [64][64]
    float* sh_we  = sh_Wp + 64 * 64;       // [64]
    float* sh_ve  = sh_we + 64;
    float* sh_b2m = sh_ve + 64;
    float* sh_b2p = sh_b2m + 64;
    int*   sh_rec = (int*)(sh_b2p + 64);   // [128]

    int tid = threadIdx.x;
    for (int i = tid; i < 64 * 64; i += 256) {
        sh_Wm[i] = msg_w2[i];
        sh_Wp[i] = mpos_w2[i];
    }
    if (tid < 64) {
        sh_we[tid]  = msg_w1[256 * 64 + tid];   // dist row of msg_w1
        sh_ve[tid]  = mpos_w1[128 * 64 + tid];  // dist row of mpos_w1
        sh_b2m[tid] = msg_b2[tid];
        sh_b2p[tid] = mpos_b2[tid];
    }

    int eb = blockIdx.x * 128;
    int e  = tid & 127;
    int half = tid >> 7;
    int eg = eb + e;
    bool valid = eg < E;
    int snd = 0, rcv = 0;
    if (valid) { snd = ei[eg]; rcv = ei[E + eg]; }
    if (half == 0) sh_rec[e] = rcv;
    float dist = 0.0f;
    if (valid) {
        float dx = pos[snd * 3 + 0] - pos[rcv * 3 + 0];
        float dy = pos[snd * 3 + 1] - pos[rcv * 3 + 1];
        float dz = pos[snd * 3 + 2] - pos[rcv * 3 + 2];
        dist = sqrtf(dx * dx + dy * dy + dz * dz);
    }

    // barrier: sh_we / sh_ve (written by tids 0..63) are read by ALL threads below
    __syncthreads();

    int c0 = half * 32;
    const float4* A4 = (const float4*)(g_A + (size_t)snd * 64 + c0);
    const float4* B4 = (const float4*)(g_B + (size_t)rcv * 64 + c0);
    const float4* P4 = (const float4*)(g_P + (size_t)snd * 64 + c0);
    const float4* Q4 = (const float4*)(g_Q + (size_t)rcv * 64 + c0);
    const float4* W4 = (const float4*)(sh_we + c0);
    const float4* V4 = (const float4*)(sh_ve + c0);

    #pragma unroll
    for (int j = 0; j < 8; j++) {
        float4 a = A4[j], b = B4[j], w = W4[j];
        float* dst = sh_h1t + (c0 + 4 * j) * 132 + e;
        dst[0]   = silu_f(a.x + b.x + dist * w.x);
        dst[132] = silu_f(a.y + b.y + dist * w.y);
        dst[264] = silu_f(a.z + b.z + dist * w.z);
        dst[396] = silu_f(a.w + b.w + dist * w.w);
    }
    #pragma unroll
    for (int j = 0; j < 8; j++) {
        float4 p = P4[j], q = Q4[j], v = V4[j];
        float* dst = sh_g1t + (c0 + 4 * j) * 132 + e;
        dst[0]   = tanh_f(p.x + q.x + dist * v.x);
        dst[132] = tanh_f(p.y + q.y + dist * v.y);
        dst[264] = tanh_f(p.z + q.z + dist * v.z);
        dst[396] = tanh_f(p.w + q.w + dist * v.w);
    }
    __syncthreads();

    int tr = tid & 31, tc = tid >> 5;      // 4 edges x 8 channels per thread
    int ebase = 4 * tr, cb = 8 * tc;
    edge_gemm_path<false>(sh_h1t, sh_Wm, sh_b2m, sh_rec, g_aggr,  ebase, cb, eb, E);
    edge_gemm_path<true >(sh_g1t, sh_Wp, sh_b2p, sh_rec, g_aggrp, ebase, cb, eb, E);
}

// ============================================================
// Kernel 3: node update MLPs -> d_out
// ============================================================
template <int K>
__device__ __forceinline__ void gemm_tile_4x4(
    const float* inT, const float* W, int ncol, int cbl, ull_t acc[4][2])
{
    #pragma unroll
    for (int i = 0; i < 4; i++) { acc[i][0] = 0ULL; acc[i][1] = 0ULL; }
    #pragma unroll 8
    for (int k = 0; k < K; k++) {
        float4 h = *(const float4*)(inT + k * 68 + ncol);
        ulonglong2 w = *(const ulonglong2*)(W + k * 64 + cbl);
        ull_t h0 = pack2(h.x, h.x), h1 = pack2(h.y, h.y);
        ull_t h2 = pack2(h.z, h.z), h3 = pack2(h.w, h.w);
        acc[0][0] = ffma2(h0, w.x, acc[0][0]); acc[0][1] = ffma2(h0, w.y, acc[0][1]);
        acc[1][0] = ffma2(h1, w.x, acc[1][0]); acc[1][1] = ffma2(h1, w.y, acc[1][1]);
        acc[2][0] = ffma2(h2, w.x, acc[2][0]); acc[2][1] = ffma2(h2, w.y, acc[2][1]);
        acc[3][0] = ffma2(h3, w.x, acc[3][0]); acc[3][1] = ffma2(h3, w.y, acc[3][1]);
    }
}

__global__ void __launch_bounds__(256, 1) node_upd_kernel(
    const float* __restrict__ x, const float* __restrict__ pe,
    const float* __restrict__ upd_w1, const float* __restrict__ upd_b1,
    const float* __restrict__ upd_w2, const float* __restrict__ upd_b2,
    const float* __restrict__ upe_w1, const float* __restrict__ upe_b1,
    const float* __restrict__ upe_w2, const float* __restrict__ upe_b2,
    float* __restrict__ out, int N)
{
    extern __shared__ float sm[];
    float* sh_inT = sm;                    // [192][68]
    float* sh_W1  = sh_inT + 192 * 68;     // [192][64]
    float* sh_hT  = sh_W1 + 192 * 64;      // [64][68]
    float* sh_W2  = sh_hT + 64 * 68;       // [64][64]
    float* sh_b1  = sh_W2 + 64 * 64;       // [64]
    float* sh_b2  = sh_b1 + 64;            // [64]

    int tid = threadIdx.x;
    int nb = blockIdx.x * 64;
    int n = tid & 63, q = tid >> 6;
    int gn = nb + n;
    bool v = gn < N;
    int tr = tid & 15, tc = tid >> 4;
    int ncol = 4 * tr, cbl = 4 * tc;

    // ---------- path 1: update = silu([x,pe,aggr]@W1+b1)@W2+b2 ----------
    for (int i = tid; i < 192 * 64; i += 256) sh_W1[i] = upd_w1[i];
    for (int i = tid; i < 64 * 64; i += 256)  sh_W2[i] = upd_w2[i];
    if (tid < 64) { sh_b1[tid] = upd_b1[tid]; sh_b2[tid] = upd_b2[tid]; }
    #pragma unroll
    for (int kk = 0; kk < 48; kk++) {
        int k = q * 48 + kk;
        float val = 0.0f;
        if (v) val = (k < 64) ? x[(size_t)gn * 64 + k]
                   : (k < 128) ? pe[(size_t)gn * 64 + (k - 64)]
                   : g_aggr[(size_t)gn * 64 + (k - 128)];
        sh_inT[k * 68 + n] = val;
    }
    __syncthreads();
    {
        ull_t acc[4][2];
        gemm_tile_4x4<192>(sh_inT, sh_W1, ncol, cbl, acc);
        float o[4][4];
        #pragma unroll
        for (int i = 0; i < 4; i++) {
            unpack2(acc[i][0], o[i][0], o[i][1]);
            unpack2(acc[i][1], o[i][2], o[i][3]);
        }
        #pragma unroll
        for (int j = 0; j < 4; j++) {
            float bj = sh_b1[cbl + j];
            float4 col = make_float4(silu_f(o[0][j] + bj), silu_f(o[1][j] + bj),
                                     silu_f(o[2][j] + bj), silu_f(o[3][j] + bj));
            *(float4*)(sh_hT + (cbl + j) * 68 + ncol) = col;
        }
    }
    __syncthreads();
    {
        ull_t acc[4][2];
        gemm_tile_4x4<64>(sh_hT, sh_W2, ncol, cbl, acc);
        float b0 = sh_b2[cbl], b1 = sh_b2[cbl + 1], b2 = sh_b2[cbl + 2], b3 = sh_b2[cbl + 3];
        #pragma unroll
        for (int i = 0; i < 4; i++) {
            int g = nb + ncol + i;
            if (g < N) {
                float o0, o1, o2, o3;
                unpack2(acc[i][0], o0, o1);
                unpack2(acc[i][1], o2, o3);
                *(float4*)(out + (size_t)g * 64 + cbl) =
                    make_float4(o0 + b0, o1 + b1, o2 + b2, o3 + b3);
            }
        }
    }
    __syncthreads();

    // ---------- path 2: update_pe = tanh(tanh([pe,aggrp]@W1+b1)@W2+b2) ----------
    for (int i = tid; i < 128 * 64; i += 256) sh_W1[i] = upe_w1[i];
    for (int i = tid; i < 64 * 64; i += 256)  sh_W2[i] = upe_w2[i];
    if (tid < 64) { sh_b1[tid] = upe_b1[tid]; sh_b2[tid] = upe_b2[tid]; }
    #pragma unroll
    for (int kk = 0; kk < 32; kk++) {
        int k = q * 32 + kk;
        float val = 0.0f;
        if (v) val = (k < 64) ? pe[(size_t)gn * 64 + k]
                              : g_aggrp[(size_t)gn * 64 + (k - 64)];
        sh_inT[k * 68 + n] = val;
    }
    __syncthreads();
    {
        ull_t acc[4][2];
        gemm_tile_4x4<128>(sh_inT, sh_W1, ncol, cbl, acc);
        float o[4][4];
        #pragma unroll
        for (int i = 0; i < 4; i++) {
            unpack2(acc[i][0], o[i][0], o[i][1]);
            unpack2(acc[i][1], o[i][2], o[i][3]);
        }
        #pragma unroll
        for (int j = 0; j < 4; j++) {
            float bj = sh_b1[cbl + j];
            float4 col = make_float4(tanh_f(o[0][j] + bj), tanh_f(o[1][j] + bj),
                                     tanh_f(o[2][j] + bj), tanh_f(o[3][j] + bj));
            *(float4*)(sh_hT + (cbl + j) * 68 + ncol) = col;
        }
    }
    __syncthreads();
    {
        ull_t acc[4][2];
        gemm_tile_4x4<64>(sh_hT, sh_W2, ncol, cbl, acc);
        float b0 = sh_b2[cbl], b1 = sh_b2[cbl + 1], b2 = sh_b2[cbl + 2], b3 = sh_b2[cbl + 3];
        float* out2 = out + (size_t)N * 64;
        #pragma unroll
        for (int i = 0; i < 4; i++) {
            int g = nb + ncol + i;
            if (g < N) {
                float o0, o1, o2, o3;
                unpack2(acc[i][0], o0, o1);
                unpack2(acc[i][1], o2, o3);
                *(float4*)(out2 + (size_t)g * 64 + cbl) =
                    make_float4(tanh_f(o0 + b0), tanh_f(o1 + b1),
                                tanh_f(o2 + b2), tanh_f(o3 + b3));
            }
        }
    }
}

// ============================================================
// Host launch
// ============================================================
extern "C" void kernel_launch(void* const* d_in, const int* in_sizes, int n_in,
                              void* d_out, int out_size)
{
    const float* x       = (const float*)d_in[0];
    const float* pos     = (const float*)d_in[1];
    const float* pe      = (const float*)d_in[2];
    const int*   ei      = (const int*)d_in[3];   // int32 (JAX x64 disabled)
    const float* msg_w1  = (const float*)d_in[4];
    const float* msg_b1  = (const float*)d_in[5];
    const float* msg_w2  = (const float*)d_in[6];
    const float* msg_b2  = (const float*)d_in[7];
    const float* mpos_w1 = (const float*)d_in[8];
    const float* mpos_b1 = (const float*)d_in[9];
    const float* mpos_w2 = (const float*)d_in[10];
    const float* mpos_b2 = (const float*)d_in[11];
    const float* upd_w1  = (const float*)d_in[12];
    const float* upd_b1  = (const float*)d_in[13];
    const float* upd_w2  = (const float*)d_in[14];
    const float* upd_b2  = (const float*)d_in[15];
    const float* upe_w1  = (const float*)d_in[16];
    const float* upe_b1  = (const float*)d_in[17];
    const float* upe_w2  = (const float*)d_in[18];
    const float* upe_b2  = (const float*)d_in[19];

    int N = in_sizes[0] / 64;
    int E = in_sizes[3] / 2;

    const int SMEM_PRE  = (128 * 68 + 128 * 256 + 256) * 4;                     // 166912 B
    const int SMEM_EDGE = (64 * 132 * 2 + 64 * 64 * 2 + 256) * 4 + 128 * 4;     // 101888 B
    const int SMEM_UPD  = (192 * 68 + 192 * 64 + 64 * 68 + 64 * 64 + 128) * 4;  // 135680 B

    cudaFuncSetAttribute(node_pre_kernel, cudaFuncAttributeMaxDynamicSharedMemorySize, SMEM_PRE);
    cudaFuncSetAttribute(edge_kernel,     cudaFuncAttributeMaxDynamicSharedMemorySize, SMEM_EDGE);
    cudaFuncSetAttribute(node_upd_kernel, cudaFuncAttributeMaxDynamicSharedMemorySize, SMEM_UPD);

    node_pre_kernel<<<(N + 63) / 64, 256, SMEM_PRE>>>(x, pe, msg_w1, msg_b1, mpos_w1, mpos_b1, N);
    edge_kernel<<<(E + 127) / 128, 256, SMEM_EDGE>>>(pos, ei, msg_w1, msg_w2, msg_b2,
                                                     mpos_w1, mpos_w2, mpos_b2, E);
    node_upd_kernel<<<(N + 63) / 64, 256, SMEM_UPD>>>(x, pe,
                                                      upd_w1, upd_b1, upd_w2, upd_b2,
                                                      upe_w1, upe_b1, upe_w2, upe_b2,
                                                      (float*)d_out, N);
}

// round 6
// speedup vs baseline: 1.0871x; 1.0871x over previous
#include <cuda_runtime.h>

#define NV_MAX 50000
#define HDIM 64

// -------- scratch (no allocs allowed) --------
__device__ float g_A[NV_MAX * HDIM];      // x@W0 + pe@W1   (msg, send side)
__device__ float g_B[NV_MAX * HDIM];      // x@W2 + pe@W3   (msg, recv side)
__device__ float g_P[NV_MAX * HDIM];      // pe@V0          (pos, send side)
__device__ float g_Q[NV_MAX * HDIM];      // pe@V1          (pos, recv side)
__device__ float g_aggr[NV_MAX * HDIM];
__device__ float g_aggrp[NV_MAX * HDIM];

typedef unsigned long long ull_t;

__device__ __forceinline__ ull_t pack2(float lo, float hi) {
    ull_t r; asm("mov.b64 %0, {%1, %2};" : "=l"(r) : "f"(lo), "f"(hi)); return r;
}
__device__ __forceinline__ void unpack2(ull_t v, float& lo, float& hi) {
    asm("mov.b64 {%0, %1}, %2;" : "=f"(lo), "=f"(hi) : "l"(v));
}
__device__ __forceinline__ ull_t ffma2(ull_t a, ull_t b, ull_t c) {
    ull_t d; asm("fma.rn.f32x2 %0, %1, %2, %3;" : "=l"(d) : "l"(a), "l"(b), "l"(c)); return d;
}
__device__ __forceinline__ float silu_f(float x) {
    return __fdividef(x, 1.0f + __expf(-x));
}
__device__ __forceinline__ float tanh_f(float x) {
    float t = __expf(2.0f * x);
    return 1.0f - 2.0f * __fdividef(1.0f, t + 1.0f);
}

// ------------------------------------------------------------
// Shared GEMM tile: 4 nodes x 8 cols per thread, sh_W row = 128 cols
// ------------------------------------------------------------
template <int K>
__device__ __forceinline__ void gemm_4x8_w128(
    const float* inT, const float* W, int ncol, int cb, ull_t acc[4][4])
{
    #pragma unroll 8
    for (int k = 0; k < K; k++) {
        float4 h = *(const float4*)(inT + k * 68 + ncol);
        ulonglong2 w0 = *(const ulonglong2*)(W + k * 128 + cb);
        ulonglong2 w1 = *(const ulonglong2*)(W + k * 128 + cb + 4);
        ull_t h0 = pack2(h.x, h.x), h1 = pack2(h.y, h.y);
        ull_t h2 = pack2(h.z, h.z), h3 = pack2(h.w, h.w);
        acc[0][0] = ffma2(h0, w0.x, acc[0][0]); acc[0][1] = ffma2(h0, w0.y, acc[0][1]);
        acc[0][2] = ffma2(h0, w1.x, acc[0][2]); acc[0][3] = ffma2(h0, w1.y, acc[0][3]);
        acc[1][0] = ffma2(h1, w0.x, acc[1][0]); acc[1][1] = ffma2(h1, w0.y, acc[1][1]);
        acc[1][2] = ffma2(h1, w1.x, acc[1][2]); acc[1][3] = ffma2(h1, w1.y, acc[1][3]);
        acc[2][0] = ffma2(h2, w0.x, acc[2][0]); acc[2][1] = ffma2(h2, w0.y, acc[2][1]);
        acc[2][2] = ffma2(h2, w1.x, acc[2][2]); acc[2][3] = ffma2(h2, w1.y, acc[2][3]);
        acc[3][0] = ffma2(h3, w0.x, acc[3][0]); acc[3][1] = ffma2(h3, w0.y, acc[3][1]);
        acc[3][2] = ffma2(h3, w1.x, acc[3][2]); acc[3][3] = ffma2(h3, w1.y, acc[3][3]);
    }
}

// ============================================================
// Kernel 1a: pre_AB — A,B projections (+ zero aggr buffers)
//   64 nodes/CTA, K=128 ([x,pe]), 128 out cols (A:0..63, B:64..127)
// ============================================================
__global__ void __launch_bounds__(256, 2) pre_AB_kernel(
    const float* __restrict__ x, const float* __restrict__ pe,
    const float* __restrict__ msg_w1, const float* __restrict__ msg_b1,
    int N)
{
    extern __shared__ float sm[];
    float* sh_inT = sm;                   // [128][68]
    float* sh_W   = sh_inT + 128 * 68;    // [128][128]
    float* sh_b   = sh_W + 128 * 128;     // [128]

    int tid = threadIdx.x;
    // W[k][c]: c<64 -> msg_w1[k][c] (A); else msg_w1[128+k][c-64] (B)
    for (int idx = tid; idx < 128 * 128; idx += 256) {
        int k = idx >> 7, c = idx & 127;
        sh_W[idx] = (c < 64) ? msg_w1[k * 64 + c]
                             : msg_w1[(128 + k) * 64 + (c - 64)];
    }
    if (tid < 128) sh_b[tid] = (tid < 64) ? msg_b1[tid] : 0.0f;

    int nb = blockIdx.x * 64;
    {
        int n = tid & 63, q = tid >> 6;
        int gn = nb + n;
        bool v = gn < N;
        #pragma unroll
        for (int kk = 0; kk < 32; kk++) {
            int k = q * 32 + kk;
            float val = 0.0f;
            if (v) val = (k < 64) ? x[(size_t)gn * 64 + k]
                                  : pe[(size_t)gn * 64 + (k - 64)];
            sh_inT[k * 68 + n] = val;
        }
        if (v) {  // zero aggregation buffers (runs before edge kernel)
            float4 z = make_float4(0.f, 0.f, 0.f, 0.f);
            float4* a4 = (float4*)(g_aggr  + (size_t)gn * 64) + q * 4;
            float4* p4 = (float4*)(g_aggrp + (size_t)gn * 64) + q * 4;
            #pragma unroll
            for (int j = 0; j < 4; j++) { a4[j] = z; p4[j] = z; }
        }
    }
    __syncthreads();

    int tr = tid & 15, tc = tid >> 4;     // 4 nodes x 8 cols
    int ncol = 4 * tr, cb = 8 * tc;

    ull_t acc[4][4];
    #pragma unroll
    for (int i = 0; i < 4; i++)
        #pragma unroll
        for (int j = 0; j < 4; j++) acc[i][j] = 0ULL;

    gemm_4x8_w128<128>(sh_inT, sh_W, ncol, cb, acc);

    float* dst = (tc < 8) ? g_A : g_B;
    int lc = (tc < 8) ? cb : (cb - 64);
    float bv[8];
    #pragma unroll
    for (int j = 0; j < 8; j++) bv[j] = sh_b[cb + j];

    #pragma unroll
    for (int i = 0; i < 4; i++) {
        int gn = nb + ncol + i;
        if (gn < N) {
            float o[8];
            unpack2(acc[i][0], o[0], o[1]);
            unpack2(acc[i][1], o[2], o[3]);
            unpack2(acc[i][2], o[4], o[5]);
            unpack2(acc[i][3], o[6], o[7]);
            #pragma unroll
            for (int j = 0; j < 8; j++) o[j] += bv[j];
            float4* d4 = (float4*)(dst + (size_t)gn * 64 + lc);
            d4[0] = make_float4(o[0], o[1], o[2], o[3]);
            d4[1] = make_float4(o[4], o[5], o[6], o[7]);
        }
    }
}

// ============================================================
// Kernel 1b: pre_PQ — P,Q projections; 64 nodes/CTA, K=64 (pe)
// ============================================================
__global__ void __launch_bounds__(256, 3) pre_PQ_kernel(
    const float* __restrict__ pe,
    const float* __restrict__ mpos_w1, const float* __restrict__ mpos_b1,
    int N)
{
    extern __shared__ float sm[];
    float* sh_inT = sm;                   // [64][68]
    float* sh_W   = sh_inT + 64 * 68;     // [64][128]
    float* sh_b   = sh_W + 64 * 128;      // [128]

    int tid = threadIdx.x;
    for (int idx = tid; idx < 64 * 128; idx += 256) {
        int k = idx >> 7, c = idx & 127;
        sh_W[idx] = (c < 64) ? mpos_w1[k * 64 + c]
                             : mpos_w1[(64 + k) * 64 + (c - 64)];
    }
    if (tid < 128) sh_b[tid] = (tid < 64) ? mpos_b1[tid] : 0.0f;

    int nb = blockIdx.x * 64;
    {
        int n = tid & 63, q = tid >> 6;
        int gn = nb + n;
        bool v = gn < N;
        #pragma unroll
        for (int kk = 0; kk < 16; kk++) {
            int k = q * 16 + kk;
            sh_inT[k * 68 + n] = v ? pe[(size_t)gn * 64 + k] : 0.0f;
        }
    }
    __syncthreads();

    int tr = tid & 15, tc = tid >> 4;
    int ncol = 4 * tr, cb = 8 * tc;

    ull_t acc[4][4];
    #pragma unroll
    for (int i = 0; i < 4; i++)
        #pragma unroll
        for (int j = 0; j < 4; j++) acc[i][j] = 0ULL;

    gemm_4x8_w128<64>(sh_inT, sh_W, ncol, cb, acc);

    float* dst = (tc < 8) ? g_P : g_Q;
    int lc = (tc < 8) ? cb : (cb - 64);
    float bv[8];
    #pragma unroll
    for (int j = 0; j < 8; j++) bv[j] = sh_b[cb + j];

    #pragma unroll
    for (int i = 0; i < 4; i++) {
        int gn = nb + ncol + i;
        if (gn < N) {
            float o[8];
            unpack2(acc[i][0], o[0], o[1]);
            unpack2(acc[i][1], o[2], o[3]);
            unpack2(acc[i][2], o[4], o[5]);
            unpack2(acc[i][3], o[6], o[7]);
            #pragma unroll
            for (int j = 0; j < 8; j++) o[j] += bv[j];
            float4* d4 = (float4*)(dst + (size_t)gn * 64 + lc);
            d4[0] = make_float4(o[0], o[1], o[2], o[3]);
            d4[1] = make_float4(o[4], o[5], o[6], o[7]);
        }
    }
}

// ============================================================
// Kernel 2: edge kernel — two sequential paths sharing ONE tile
// ============================================================
template <bool IS_TANH>
__device__ __forceinline__ void edge_gemm_path(
    const float* hT, const float* W, const float* bias, const int* recs,
    float* __restrict__ aggr, int ebase, int cb, int eb, int E)
{
    ull_t acc[4][4];
    #pragma unroll
    for (int i = 0; i < 4; i++)
        #pragma unroll
        for (int j = 0; j < 4; j++) acc[i][j] = 0ULL;

    #pragma unroll 8
    for (int k = 0; k < 64; k++) {
        float4 h = *(const float4*)(hT + k * 132 + ebase);
        ulonglong2 w0 = *(const ulonglong2*)(W + k * 64 + cb);
        ulonglong2 w1 = *(const ulonglong2*)(W + k * 64 + cb + 4);
        ull_t h0 = pack2(h.x, h.x), h1 = pack2(h.y, h.y);
        ull_t h2 = pack2(h.z, h.z), h3 = pack2(h.w, h.w);
        acc[0][0] = ffma2(h0, w0.x, acc[0][0]); acc[0][1] = ffma2(h0, w0.y, acc[0][1]);
        acc[0][2] = ffma2(h0, w1.x, acc[0][2]); acc[0][3] = ffma2(h0, w1.y, acc[0][3]);
        acc[1][0] = ffma2(h1, w0.x, acc[1][0]); acc[1][1] = ffma2(h1, w0.y, acc[1][1]);
        acc[1][2] = ffma2(h1, w1.x, acc[1][2]); acc[1][3] = ffma2(h1, w1.y, acc[1][3]);
        acc[2][0] = ffma2(h2, w0.x, acc[2][0]); acc[2][1] = ffma2(h2, w0.y, acc[2][1]);
        acc[2][2] = ffma2(h2, w1.x, acc[2][2]); acc[2][3] = ffma2(h2, w1.y, acc[2][3]);
        acc[3][0] = ffma2(h3, w0.x, acc[3][0]); acc[3][1] = ffma2(h3, w0.y, acc[3][1]);
        acc[3][2] = ffma2(h3, w1.x, acc[3][2]); acc[3][3] = ffma2(h3, w1.y, acc[3][3]);
    }

    float bsv[8];
    #pragma unroll
    for (int j = 0; j < 8; j++) bsv[j] = bias[cb + j];

    #pragma unroll
    for (int i = 0; i < 4; i++) {
        int el = ebase + i;
        if (eb + el < E) {
            float m[8];
            unpack2(acc[i][0], m[0], m[1]);
            unpack2(acc[i][1], m[2], m[3]);
            unpack2(acc[i][2], m[4], m[5]);
            unpack2(acc[i][3], m[6], m[7]);
            #pragma unroll
            for (int j = 0; j < 8; j++) {
                float v = m[j] + bsv[j];
                m[j] = IS_TANH ? tanh_f(v) : silu_f(v);
            }
            float* dst = aggr + (size_t)recs[el] * 64 + cb;
            asm volatile("red.global.add.v4.f32 [%0], {%1,%2,%3,%4};"
                         :: "l"(dst), "f"(m[0]), "f"(m[1]), "f"(m[2]), "f"(m[3]) : "memory");
            asm volatile("red.global.add.v4.f32 [%0], {%1,%2,%3,%4};"
                         :: "l"(dst + 4), "f"(m[4]), "f"(m[5]), "f"(m[6]), "f"(m[7]) : "memory");
        }
    }
}

__global__ void __launch_bounds__(256, 3) edge_kernel(
    const float* __restrict__ pos,
    const int* __restrict__ ei,          // int32 (JAX demotes int64)
    const float* __restrict__ msg_w1,
    const float* __restrict__ msg_w2, const float* __restrict__ msg_b2,
    const float* __restrict__ mpos_w1,
    const float* __restrict__ mpos_w2, const float* __restrict__ mpos_b2,
    int E)
{
    extern __shared__ float sm[];
    float* sh_t   = sm;                    // [64][132] (reused by both paths)
    float* sh_Wm  = sh_t + 64 * 132;       // [64][64]
    float* sh_Wp  = sh_Wm + 64 * 64;       // [64][64]
    float* sh_we  = sh_Wp + 64 * 64;       // [64]
    float* sh_ve  = sh_we + 64;
    float* sh_bm  = sh_ve + 64;
    float* sh_bp  = sh_bm + 64;
    int*   sh_rec = (int*)(sh_bp + 64);    // [128]

    int tid = threadIdx.x;
    for (int i = tid; i < 64 * 64; i += 256) {
        sh_Wm[i] = msg_w2[i];
        sh_Wp[i] = mpos_w2[i];
    }
    if (tid < 64) {
        sh_we[tid] = msg_w1[256 * 64 + tid];   // dist row of msg_w1
        sh_ve[tid] = mpos_w1[128 * 64 + tid];  // dist row of mpos_w1
        sh_bm[tid] = msg_b2[tid];
        sh_bp[tid] = mpos_b2[tid];
    }

    int eb = blockIdx.x * 128;
    int e  = tid & 127;
    int half = tid >> 7;
    int eg = eb + e;
    bool valid = eg < E;
    int snd = 0, rcv = 0;
    if (valid) { snd = ei[eg]; rcv = ei[E + eg]; }
    if (half == 0) sh_rec[e] = rcv;
    float dist = 0.0f;
    if (valid) {
        float dx = pos[snd * 3 + 0] - pos[rcv * 3 + 0];
        float dy = pos[snd * 3 + 1] - pos[rcv * 3 + 1];
        float dz = pos[snd * 3 + 2] - pos[rcv * 3 + 2];
        dist = sqrtf(dx * dx + dy * dy + dz * dz);
    }
    __syncthreads();   // weights + rec visible to all

    int c0 = half * 32;
    int tr = tid & 31, tc = tid >> 5;      // GEMM map: 4 edges x 8 cols
    int ebase = 4 * tr, cb = 8 * tc;

    // ---- phase A: silu(A[snd]+B[rcv]+dist*we) tile, msg path ----
    {
        const float4* A4 = (const float4*)(g_A + (size_t)snd * 64 + c0);
        const float4* B4 = (const float4*)(g_B + (size_t)rcv * 64 + c0);
        const float4* W4 = (const float4*)(sh_we + c0);
        #pragma unroll
        for (int j = 0; j < 8; j++) {
            float4 a = A4[j], b = B4[j], w = W4[j];
            float* dst = sh_t + (c0 + 4 * j) * 132 + e;
            dst[0]   = silu_f(a.x + b.x + dist * w.x);
            dst[132] = silu_f(a.y + b.y + dist * w.y);
            dst[264] = silu_f(a.z + b.z + dist * w.z);
            dst[396] = silu_f(a.w + b.w + dist * w.w);
        }
    }
    __syncthreads();
    edge_gemm_path<false>(sh_t, sh_Wm, sh_bm, sh_rec, g_aggr, ebase, cb, eb, E);
    __syncthreads();   // all reads of sh_t done before overwrite

    // ---- phase B: tanh(P[snd]+Q[rcv]+dist*ve) tile, pos path ----
    {
        const float4* P4 = (const float4*)(g_P + (size_t)snd * 64 + c0);
        const float4* Q4 = (const float4*)(g_Q + (size_t)rcv * 64 + c0);
        const float4* V4 = (const float4*)(sh_ve + c0);
        #pragma unroll
        for (int j = 0; j < 8; j++) {
            float4 p = P4[j], q = Q4[j], v = V4[j];
            float* dst = sh_t + (c0 + 4 * j) * 132 + e;
            dst[0]   = tanh_f(p.x + q.x + dist * v.x);
            dst[132] = tanh_f(p.y + q.y + dist * v.y);
            dst[264] = tanh_f(p.z + q.z + dist * v.z);
            dst[396] = tanh_f(p.w + q.w + dist * v.w);
        }
    }
    __syncthreads();
    edge_gemm_path<true>(sh_t, sh_Wp, sh_bp, sh_rec, g_aggrp, ebase, cb, eb, E);
}

// ============================================================
// Kernel 3 helpers: 4 nodes x 4 cols tile, sh_W row = 64 cols
// ============================================================
template <int K>
__device__ __forceinline__ void gemm_4x4_w64(
    const float* inT, const float* W, int ncol, int cbl, ull_t acc[4][2])
{
    #pragma unroll 8
    for (int k = 0; k < K; k++) {
        float4 h = *(const float4*)(inT + k * 68 + ncol);
        ulonglong2 w = *(const ulonglong2*)(W + k * 64 + cbl);
        ull_t h0 = pack2(h.x, h.x), h1 = pack2(h.y, h.y);
        ull_t h2 = pack2(h.z, h.z), h3 = pack2(h.w, h.w);
        acc[0][0] = ffma2(h0, w.x, acc[0][0]); acc[0][1] = ffma2(h0, w.y, acc[0][1]);
        acc[1][0] = ffma2(h1, w.x, acc[1][0]); acc[1][1] = ffma2(h1, w.y, acc[1][1]);
        acc[2][0] = ffma2(h2, w.x, acc[2][0]); acc[2][1] = ffma2(h2, w.y, acc[2][1]);
        acc[3][0] = ffma2(h3, w.x, acc[3][0]); acc[3][1] = ffma2(h3, w.y, acc[3][1]);
    }
}

// ============================================================
// Kernel 3a: update = silu([x,pe,aggr]@W1+b1)@W2+b2   (W1 K-chunked)
// ============================================================
__global__ void __launch_bounds__(256, 2) upd1_kernel(
    const float* __restrict__ x, const float* __restrict__ pe,
    const float* __restrict__ upd_w1, const float* __restrict__ upd_b1,
    const float* __restrict__ upd_w2, const float* __restrict__ upd_b2,
    float* __restrict__ out, int N)
{
    extern __shared__ float sm[];
    float* sh_inT = sm;                    // [192][68]
    float* sh_W1c = sh_inT + 192 * 68;     // [64][64] chunk
    float* sh_hT  = sh_W1c + 64 * 64;      // [64][68]
    float* sh_W2  = sh_hT + 64 * 68;       // [64][64]
    float* sh_b1  = sh_W2 + 64 * 64;       // [64]
    float* sh_b2  = sh_b1 + 64;            // [64]

    int tid = threadIdx.x;
    int nb = blockIdx.x * 64;
    int n = tid & 63, q = tid >> 6;
    int gn = nb + n;
    bool v = gn < N;
    int tr = tid & 15, tc = tid >> 4;
    int ncol = 4 * tr, cbl = 4 * tc;

    for (int i = tid; i < 64 * 64; i += 256) sh_W2[i] = upd_w2[i];
    if (tid < 64) { sh_b1[tid] = upd_b1[tid]; sh_b2[tid] = upd_b2[tid]; }
    #pragma unroll
    for (int kk = 0; kk < 48; kk++) {
        int k = q * 48 + kk;
        float val = 0.0f;
        if (v) val = (k < 64) ? x[(size_t)gn * 64 + k]
                   : (k < 128) ? pe[(size_t)gn * 64 + (k - 64)]
                   : g_aggr[(size_t)gn * 64 + (k - 128)];
        sh_inT[k * 68 + n] = val;
    }

    ull_t acc[4][2];
    #pragma unroll
    for (int i = 0; i < 4; i++) { acc[i][0] = 0ULL; acc[i][1] = 0ULL; }

    #pragma unroll 1
    for (int ch = 0; ch < 3; ch++) {
        __syncthreads();   // also covers inT/W2 on first iter; readers done on later iters
        for (int i = tid; i < 64 * 64; i += 256) sh_W1c[i] = upd_w1[ch * 64 * 64 + i];
        __syncthreads();
        gemm_4x4_w64<64>(sh_inT + (ch * 64) * 68, sh_W1c, ncol, cbl, acc);
    }
    __syncthreads();
    {
        float o[4][4];
        #pragma unroll
        for (int i = 0; i < 4; i++) {
            unpack2(acc[i][0], o[i][0], o[i][1]);
            unpack2(acc[i][1], o[i][2], o[i][3]);
        }
        #pragma unroll
        for (int j = 0; j < 4; j++) {
            float bj = sh_b1[cbl + j];
            float4 col = make_float4(silu_f(o[0][j] + bj), silu_f(o[1][j] + bj),
                                     silu_f(o[2][j] + bj), silu_f(o[3][j] + bj));
            *(float4*)(sh_hT + (cbl + j) * 68 + ncol) = col;
        }
    }
    __syncthreads();
    {
        ull_t a2[4][2];
        #pragma unroll
        for (int i = 0; i < 4; i++) { a2[i][0] = 0ULL; a2[i][1] = 0ULL; }
        gemm_4x4_w64<64>(sh_hT, sh_W2, ncol, cbl, a2);
        float b0 = sh_b2[cbl], b1 = sh_b2[cbl + 1], b2 = sh_b2[cbl + 2], b3 = sh_b2[cbl + 3];
        #pragma unroll
        for (int i = 0; i < 4; i++) {
            int g = nb + ncol + i;
            if (g < N) {
                float o0, o1, o2, o3;
                unpack2(a2[i][0], o0, o1);
                unpack2(a2[i][1], o2, o3);
                *(float4*)(out + (size_t)g * 64 + cbl) =
                    make_float4(o0 + b0, o1 + b1, o2 + b2, o3 + b3);
            }
        }
    }
}

// ============================================================
// Kernel 3b: update_pe = tanh(tanh([pe,aggrp]@W1+b1)@W2+b2)
// ============================================================
__global__ void __launch_bounds__(256, 2) upd2_kernel(
    const float* __restrict__ pe,
    const float* __restrict__ upe_w1, const float* __restrict__ upe_b1,
    const float* __restrict__ upe_w2, const float* __restrict__ upe_b2,
    float* __restrict__ out, int N)
{
    extern __shared__ float sm[];
    float* sh_inT = sm;                    // [128][68]
    float* sh_W1  = sh_inT + 128 * 68;     // [128][64]
    float* sh_hT  = sh_W1 + 128 * 64;      // [64][68]
    float* sh_W2  = sh_hT + 64 * 68;       // [64][64]
    float* sh_b1  = sh_W2 + 64 * 64;
    float* sh_b2  = sh_b1 + 64;

    int tid = threadIdx.x;
    int nb = blockIdx.x * 64;
    int n = tid & 63, q = tid >> 6;
    int gn = nb + n;
    bool v = gn < N;
    int tr = tid & 15, tc = tid >> 4;
    int ncol = 4 * tr, cbl = 4 * tc;

    for (int i = tid; i < 128 * 64; i += 256) sh_W1[i] = upe_w1[i];
    for (int i = tid; i < 64 * 64; i += 256)  sh_W2[i] = upe_w2[i];
    if (tid < 64) { sh_b1[tid] = upe_b1[tid]; sh_b2[tid] = upe_b2[tid]; }
    #pragma unroll
    for (int kk = 0; kk < 32; kk++) {
        int k = q * 32 + kk;
        float val = 0.0f;
        if (v) val = (k < 64) ? pe[(size_t)gn * 64 + k]
                              : g_aggrp[(size_t)gn * 64 + (k - 64)];
        sh_inT[k * 68 + n] = val;
    }
    __syncthreads();
    {
        ull_t acc[4][2];
        #pragma unroll
        for (int i = 0; i < 4; i++) { acc[i][0] = 0ULL; acc[i][1] = 0ULL; }
        gemm_4x4_w64<128>(sh_inT, sh_W1, ncol, cbl, acc);
        float o[4][4];
        #pragma unroll
        for (int i = 0; i < 4; i++) {
            unpack2(acc[i][0], o[i][0], o[i][1]);
            unpack2(acc[i][1], o[i][2], o[i][3]);
        }
        #pragma unroll
        for (int j = 0; j < 4; j++) {
            float bj = sh_b1[cbl + j];
            float4 col = make_float4(tanh_f(o[0][j] + bj), tanh_f(o[1][j] + bj),
                                     tanh_f(o[2][j] + bj), tanh_f(o[3][j] + bj));
            *(float4*)(sh_hT + (cbl + j) * 68 + ncol) = col;
        }
    }
    __syncthreads();
    {
        ull_t acc[4][2];
        #pragma unroll
        for (int i = 0; i < 4; i++) { acc[i][0] = 0ULL; acc[i][1] = 0ULL; }
        gemm_4x4_w64<64>(sh_hT, sh_W2, ncol, cbl, acc);
        float b0 = sh_b2[cbl], b1 = sh_b2[cbl + 1], b2 = sh_b2[cbl + 2], b3 = sh_b2[cbl + 3];
        float* out2 = out + (size_t)N * 64;
        #pragma unroll
        for (int i = 0; i < 4; i++) {
            int g = nb + ncol + i;
            if (g < N) {
                float o0, o1, o2, o3;
                unpack2(acc[i][0], o0, o1);
                unpack2(acc[i][1], o2, o3);
                *(float4*)(out2 + (size_t)g * 64 + cbl) =
                    make_float4(tanh_f(o0 + b0), tanh_f(o1 + b1),
                                tanh_f(o2 + b2), tanh_f(o3 + b3));
            }
        }
    }
}

// ============================================================
// Host launch
// ============================================================
extern "C" void kernel_launch(void* const* d_in, const int* in_sizes, int n_in,
                              void* d_out, int out_size)
{
    const float* x       = (const float*)d_in[0];
    const float* pos     = (const float*)d_in[1];
    const float* pe      = (const float*)d_in[2];
    const int*   ei      = (const int*)d_in[3];
    const float* msg_w1  = (const float*)d_in[4];
    const float* msg_b1  = (const float*)d_in[5];
    const float* msg_w2  = (const float*)d_in[6];
    const float* msg_b2  = (const float*)d_in[7];
    const float* mpos_w1 = (const float*)d_in[8];
    const float* mpos_b1 = (const float*)d_in[9];
    const float* mpos_w2 = (const float*)d_in[10];
    const float* mpos_b2 = (const float*)d_in[11];
    const float* upd_w1  = (const float*)d_in[12];
    const float* upd_b1  = (const float*)d_in[13];
    const float* upd_w2  = (const float*)d_in[14];
    const float* upd_b2  = (const float*)d_in[15];
    const float* upe_w1  = (const float*)d_in[16];
    const float* upe_b1  = (const float*)d_in[17];
    const float* upe_w2  = (const float*)d_in[18];
    const float* upe_b2  = (const float*)d_in[19];

    int N = in_sizes[0] / 64;
    int E = in_sizes[3] / 2;

    const int SMEM_AB   = (128 * 68 + 128 * 128 + 128) * 4;                 // 100,608 B
    const int SMEM_PQ   = (64 * 68 + 64 * 128 + 128) * 4;                   //  50,688 B
    const int SMEM_EDGE = (64 * 132 + 64 * 64 * 2 + 256) * 4 + 128 * 4;     //  68,096 B
    const int SMEM_U1   = (192 * 68 + 64 * 64 + 64 * 68 + 64 * 64 + 128) * 4; // 102,912 B
    const int SMEM_U2   = (128 * 68 + 128 * 64 + 64 * 68 + 64 * 64 + 128) * 4; // 101,888 B

    cudaFuncSetAttribute(pre_AB_kernel, cudaFuncAttributeMaxDynamicSharedMemorySize, SMEM_AB);
    cudaFuncSetAttribute(pre_PQ_kernel, cudaFuncAttributeMaxDynamicSharedMemorySize, SMEM_PQ);
    cudaFuncSetAttribute(edge_kernel,   cudaFuncAttributeMaxDynamicSharedMemorySize, SMEM_EDGE);
    cudaFuncSetAttribute(upd1_kernel,   cudaFuncAttributeMaxDynamicSharedMemorySize, SMEM_U1);
    cudaFuncSetAttribute(upd2_kernel,   cudaFuncAttributeMaxDynamicSharedMemorySize, SMEM_U2);

    int gn = (N + 63) / 64;
    pre_AB_kernel<<<gn, 256, SMEM_AB>>>(x, pe, msg_w1, msg_b1, N);
    pre_PQ_kernel<<<gn, 256, SMEM_PQ>>>(pe, mpos_w1, mpos_b1, N);
    edge_kernel<<<(E + 127) / 128, 256, SMEM_EDGE>>>(pos, ei, msg_w1, msg_w2, msg_b2,
                                                     mpos_w1, mpos_w2, mpos_b2, E);
    upd1_kernel<<<gn, 256, SMEM_U1>>>(x, pe, upd_w1, upd_b1, upd_w2, upd_b2, (float*)d_out, N);
    upd2_kernel<<<gn, 256, SMEM_U2>>>(pe, upe_w1, upe_b1, upe_w2, upe_b2, (float*)d_out, N);
}